// round 10
// baseline (speedup 1.0000x reference)
#include <cuda_runtime.h>
#include <cuda_fp16.h>
#include <math.h>
#include <stdint.h>

// Problem constants
#define BB   32
#define LL   512
#define HH   1024
#define QQ   128
#define BQ   (BB * QQ)        // 4096 pair rows
#define K1   (3 * HH)          // 3072
#define N1   256               // VA_H
#define N2   128               // VA_H/2

// Scratch (static device globals)
__device__ __half g_A[(size_t)BQ * K1];     // pooled pair features, fp16
__device__ __half g_W1[(size_t)N1 * K1];    // fp16 weights
__device__ __half g_W2[(size_t)N2 * N1];
__device__ __half g_x1[(size_t)BQ * N1];    // gelu(layer1), fp16
__device__ float  g_x2[(size_t)BQ * N2];

// ---------------------------------------------------------------------------
// helpers
// ---------------------------------------------------------------------------
__device__ __forceinline__ uint32_t smem_u32(const void* p) {
    uint32_t a;
    asm("{ .reg .u64 t; cvta.to.shared.u64 t, %1; cvt.u32.u64 %0, t; }"
        : "=r"(a) : "l"(p));
    return a;
}

#define CP_ASYNC16(dst, src) \
    asm volatile("cp.async.cg.shared.global [%0], [%1], 16;" :: "r"(dst), "l"(src) : "memory")
#define CP_COMMIT() asm volatile("cp.async.commit_group;" ::: "memory")
#define CP_WAIT0()  asm volatile("cp.async.wait_group 0;" ::: "memory")
#define CP_WAIT1()  asm volatile("cp.async.wait_group 1;" ::: "memory")
#define CP_WAIT2()  asm volatile("cp.async.wait_group 2;" ::: "memory")

__device__ __forceinline__ void mma16816(float c[4],
                                         const uint32_t a[4],
                                         const uint32_t b[2])
{
    asm volatile(
        "mma.sync.aligned.m16n8k16.row.col.f32.f16.f16.f32 "
        "{%0,%1,%2,%3}, {%4,%5,%6,%7}, {%8,%9}, {%0,%1,%2,%3};\n"
        : "+f"(c[0]), "+f"(c[1]), "+f"(c[2]), "+f"(c[3])
        : "r"(a[0]), "r"(a[1]), "r"(a[2]), "r"(a[3]),
          "r"(b[0]), "r"(b[1]));
}

__device__ __forceinline__ void ldsm4(uint32_t r[4], uint32_t addr)
{
    asm volatile("ldmatrix.sync.aligned.m8n8.x4.shared.b16 {%0,%1,%2,%3}, [%4];"
        : "=r"(r[0]), "=r"(r[1]), "=r"(r[2]), "=r"(r[3]) : "r"(addr));
}

__device__ __forceinline__ float gelu_exact(float x) {
    return 0.5f * x * (1.0f + erff(x * 0.70710678118654752f));
}

__device__ __forceinline__ void store_h4(__half* dst, size_t idx, float4 v)
{
    __half2 hh[2] = {
        __halves2half2(__float2half_rn(v.x), __float2half_rn(v.y)),
        __halves2half2(__float2half_rn(v.z), __float2half_rn(v.w)) };
    *(uint2*)(dst + idx) = *(uint2*)hh;
}

// ---------------------------------------------------------------------------
// Weight prep: convert W1, W2 to fp16
// ---------------------------------------------------------------------------
__global__ void prep_w_kernel(const float* __restrict__ W1,
                              const float* __restrict__ W2)
{
    const int i = blockIdx.x * blockDim.x + threadIdx.x;
    if (i < N1 * K1) g_W1[i] = __float2half_rn(W1[i]);
    if (i < N2 * N1) g_W2[i] = __float2half_rn(W2[i]);
}

// ---------------------------------------------------------------------------
// Span pooling + pair features -> fp16
// ---------------------------------------------------------------------------
__global__ void pool_pair_kernel(const float* __restrict__ hs,
                                 const int* __restrict__ spans)
{
    const int bq  = blockIdx.x;
    const int b   = bq >> 7;
    const int tid = threadIdx.x;

    const int* sp = spans + (size_t)bq * 4;
    const int as = sp[0], ae = sp[1], os = sp[2], oe = sp[3];
    const bool av = (as >= 2) && (ae >= as);
    const bool ov = (os >= 2) && (oe >= os);

    const float* base = hs + (size_t)b * LL * HH + 4 * tid;

    float4 aacc = {0.f, 0.f, 0.f, 0.f};
    float4 oacc = {0.f, 0.f, 0.f, 0.f};

    {
        int s = av ? as : 1, e = av ? ae : 1;
        s = min(max(s, 0), LL - 1);
        e = min(max(e, 0), LL - 1);
        const float inv = 1.0f / (float)((e - s + 1) > 0 ? (e - s + 1) : 1);
        for (int r = s; r <= e; ++r) {
            const float4 v = *(const float4*)(base + (size_t)r * HH);
            aacc.x += v.x; aacc.y += v.y; aacc.z += v.z; aacc.w += v.w;
        }
        aacc.x *= inv; aacc.y *= inv; aacc.z *= inv; aacc.w *= inv;
    }
    {
        int s = ov ? os : 1, e = ov ? oe : 1;
        s = min(max(s, 0), LL - 1);
        e = min(max(e, 0), LL - 1);
        const float inv = 1.0f / (float)((e - s + 1) > 0 ? (e - s + 1) : 1);
        for (int r = s; r <= e; ++r) {
            const float4 v = *(const float4*)(base + (size_t)r * HH);
            oacc.x += v.x; oacc.y += v.y; oacc.z += v.z; oacc.w += v.w;
        }
        oacc.x *= inv; oacc.y *= inv; oacc.z *= inv; oacc.w *= inv;
    }

    float4 pacc;
    pacc.x = aacc.x * oacc.x;  pacc.y = aacc.y * oacc.y;
    pacc.z = aacc.z * oacc.z;  pacc.w = aacc.w * oacc.w;

    const size_t rowoff = (size_t)bq * K1 + 4 * tid;
    store_h4(g_A, rowoff,          aacc);
    store_h4(g_A, rowoff + HH,     oacc);
    store_h4(g_A, rowoff + 2 * HH, pacc);
}

// ---------------------------------------------------------------------------
// Pipelined pure-fp16 mma.sync GEMM, fp32 accum, ldmatrix fragments.
// BM=32*MTP, BN=64*NTP, BK=32, 256 threads = 8 warps (2M x 4N).
// 3-stage cp.async pipeline.
// mode 0: out_f = gelu(acc+bias)  fp32
// mode 1: out_h = gelu(acc+bias)  fp16
// ---------------------------------------------------------------------------
template<int MTP, int NTP>
__global__ __launch_bounds__(256)
void mma_gemm_kernel(const __half* __restrict__ A,
                     const __half* __restrict__ B,
                     int lda, int ldb, int K,
                     const float* __restrict__ bias,
                     float* __restrict__ out_f,
                     __half* __restrict__ out_h,
                     int out_ld, int mode)
{
    constexpr int BM    = 32 * MTP;
    constexpr int BN    = 64 * NTP;
    constexpr int AWd   = BM * 20;          // words per A buffer
    constexpr int BWd   = BN * 20;          // words per B buffer
    constexpr int STWd  = AWd + BWd;
    constexpr int TOT16 = (BM + BN) * 4;    // 16B units per stage
    constexpr int UNITS = (TOT16 + 255) / 256;

    extern __shared__ uint32_t sm[];
    const uint32_t smem32 = smem_u32(sm);

    const int tid   = threadIdx.x;
    const int warp  = tid >> 5;
    const int lane  = tid & 31;
    const int warpM = warp >> 2;
    const int warpN = warp & 3;
    const int lane4 = lane >> 2;
    const int lanem = lane & 3;

    const int m0 = blockIdx.y * BM;
    const int n0 = blockIdx.x * BN;
    const int nk = K >> 5;

    const uint32_t aLaneOff = ((lane & 15) * 20 + ((lane >> 4) << 2)) * 4;
    const uint32_t bLaneOff = (((lane & 7) + ((lane >> 4) << 3)) * 20
                               + (((lane >> 3) & 1) << 2)) * 4;
    const uint32_t aWarpOff = (uint32_t)(warpM * (16 * MTP)) * 80;
    const uint32_t bWarpOff = (uint32_t)(warpN * (NTP * 16)) * 80;

    auto load_stage = [&](int c) {
        const uint32_t sb = smem32 + (uint32_t)(c % 3) * (STWd * 4);
        const int kk = c * 32;
        #pragma unroll
        for (int i = 0; i < UNITS; ++i) {
            const int u = i * 256 + tid;
            if (UNITS * 256 != TOT16 && u >= TOT16) break;
            const __half* src;
            uint32_t dstw;
            if (u < BM * 4) {
                const int row = u >> 2, seg = u & 3;
                src  = A + (size_t)(m0 + row) * lda + kk + seg * 8;
                dstw = row * 20 + seg * 4;
            } else {
                const int v = u - BM * 4;
                const int row = v >> 2, seg = v & 3;
                src  = B + (size_t)(n0 + row) * ldb + kk + seg * 8;
                dstw = AWd + row * 20 + seg * 4;
            }
            CP_ASYNC16(sb + dstw * 4, src);
        }
        CP_COMMIT();
    };

    float acc[MTP][2 * NTP][4];
    #pragma unroll
    for (int i = 0; i < MTP; ++i)
        #pragma unroll
        for (int j = 0; j < 2 * NTP; ++j)
            #pragma unroll
            for (int k = 0; k < 4; ++k) acc[i][j][k] = 0.f;

    // 3-stage prologue
    load_stage(0);
    if (nk > 1) load_stage(1);

    for (int c = 0; c < nk; ++c) {
        if (c + 2 < nk)      { load_stage(c + 2); CP_WAIT2(); }
        else if (c + 1 < nk) { CP_WAIT1(); }
        else                 { CP_WAIT0(); }
        __syncthreads();

        const uint32_t sb = smem32 + (uint32_t)(c % 3) * (STWd * 4);
        const uint32_t aB = sb + aWarpOff + aLaneOff;
        const uint32_t bB = sb + AWd * 4 + bWarpOff + bLaneOff;

        #pragma unroll
        for (int sub = 0; sub < 2; ++sub) {
            uint32_t af[MTP][4];
            #pragma unroll
            for (int mt = 0; mt < MTP; ++mt)
                ldsm4(af[mt], aB + (uint32_t)mt * (16 * 80) + sub * 32);

            #pragma unroll
            for (int ntp = 0; ntp < NTP; ++ntp) {
                uint32_t bf[4];
                ldsm4(bf, bB + (uint32_t)ntp * (16 * 80) + sub * 32);
                #pragma unroll
                for (int hf = 0; hf < 2; ++hf) {
                    const int nt = ntp * 2 + hf;
                    #pragma unroll
                    for (int mt = 0; mt < MTP; ++mt)
                        mma16816(acc[mt][nt], af[mt], bf + hf * 2);
                }
            }
        }
        __syncthreads();
    }

    // ---- epilogue: bias + gelu ----
    #pragma unroll
    for (int mt = 0; mt < MTP; ++mt) {
        #pragma unroll
        for (int nt = 0; nt < 2 * NTP; ++nt) {
            const int c0 = n0 + warpN * (NTP * 16) + nt * 8 + lanem * 2;
            const int r0 = m0 + warpM * (16 * MTP) + mt * 16 + lane4;
            const float bv0 = bias[c0];
            const float bv1 = bias[c0 + 1];

            const float g00 = gelu_exact(acc[mt][nt][0] + bv0);
            const float g01 = gelu_exact(acc[mt][nt][1] + bv1);
            const float g10 = gelu_exact(acc[mt][nt][2] + bv0);
            const float g11 = gelu_exact(acc[mt][nt][3] + bv1);

            if (mode == 0) {
                *(float2*)(out_f + (size_t)r0 * out_ld + c0)       = make_float2(g00, g01);
                *(float2*)(out_f + (size_t)(r0 + 8) * out_ld + c0) = make_float2(g10, g11);
            } else {
                *(__half2*)(out_h + (size_t)r0 * out_ld + c0) =
                    __halves2half2(__float2half_rn(g00), __float2half_rn(g01));
                *(__half2*)(out_h + (size_t)(r0 + 8) * out_ld + c0) =
                    __halves2half2(__float2half_rn(g10), __float2half_rn(g11));
            }
        }
    }
}

#define GEMM_SMEM ((3 * (32 * 20 + 64 * 20)) * 4)   // 23040 B (3 stages)

// ---------------------------------------------------------------------------
// Head: one warp per 8 rows, shuffle reduction over K=128
// ---------------------------------------------------------------------------
__global__ void head_kernel(const float* __restrict__ X,
                            const float* __restrict__ W3,
                            const float* __restrict__ b3,
                            const float* __restrict__ mask,
                            float* __restrict__ out)
{
    const int gwarp = (blockIdx.x * blockDim.x + threadIdx.x) >> 5;
    const int lane  = threadIdx.x & 31;

    const float4 w0 = ((const float4*)W3)[lane];
    const float4 w1 = ((const float4*)W3)[32 + lane];
    const float b30 = b3[0], b31 = b3[1];

    const int rowbase = gwarp * 8;
    #pragma unroll
    for (int i = 0; i < 8; ++i) {
        const int row = rowbase + i;
        const float4 xv = ((const float4*)(X + (size_t)row * N2))[lane];
        float s0 = xv.x * w0.x + xv.y * w0.y + xv.z * w0.z + xv.w * w0.w;
        float s1 = xv.x * w1.x + xv.y * w1.y + xv.z * w1.z + xv.w * w1.w;
        #pragma unroll
        for (int off = 16; off > 0; off >>= 1) {
            s0 += __shfl_xor_sync(0xFFFFFFFFu, s0, off);
            s1 += __shfl_xor_sync(0xFFFFFFFFu, s1, off);
        }
        if (lane == 0) {
            const float mk = (mask[row] >= 0.5f) ? 1.0f : 0.0f;
            const float v0 = (1.0f / (1.0f + expf(-(s0 + b30)))) * 8.0f + 1.0f;
            const float v1 = (1.0f / (1.0f + expf(-(s1 + b31)))) * 8.0f + 1.0f;
            out[row * 2 + 0] = v0 * mk;
            out[row * 2 + 1] = v1 * mk;
        }
    }
}

// ---------------------------------------------------------------------------
// Launch
// ---------------------------------------------------------------------------
extern "C" void kernel_launch(void* const* d_in, const int* in_sizes, int n_in,
                              void* d_out, int out_size)
{
    const float* hidden = (const float*)d_in[0];
    const int*   spans  = (const int*)d_in[1];
    const float* mask   = (const float*)d_in[2];
    const float* W1     = (const float*)d_in[3];
    const float* b1     = (const float*)d_in[4];
    const float* W2     = (const float*)d_in[5];
    const float* b2     = (const float*)d_in[6];
    const float* W3     = (const float*)d_in[7];
    const float* b3     = (const float*)d_in[8];
    float*       out    = (float*)d_out;

    __half *A, *W1h, *W2h, *x1;
    float  *x2;
    cudaGetSymbolAddress((void**)&A,   g_A);
    cudaGetSymbolAddress((void**)&W1h, g_W1);
    cudaGetSymbolAddress((void**)&W2h, g_W2);
    cudaGetSymbolAddress((void**)&x1,  g_x1);
    cudaGetSymbolAddress((void**)&x2,  g_x2);

    cudaFuncSetAttribute((const void*)mma_gemm_kernel<1, 1>,
                         cudaFuncAttributeMaxDynamicSharedMemorySize, GEMM_SMEM);

    // 0) weight prep (fp32 -> fp16)
    prep_w_kernel<<<(N1 * K1 + 255) / 256, 256>>>(W1, W2);

    // 1) pooling + pair features (fp16)
    pool_pair_kernel<<<BQ, 256>>>(hidden, spans);

    // 2) layer 1: grid (4, 128) = 512 CTAs, fused bias+gelu -> fp16 x1
    {
        dim3 grid(N1 / 64, BQ / 32);
        mma_gemm_kernel<1, 1><<<grid, 256, GEMM_SMEM>>>(
            A, W1h, K1, K1, K1, b1, nullptr, x1, N1, 1);
    }

    // 3) layer 2: grid (2, 128) = 256 CTAs, fused bias+gelu -> fp32 x2
    {
        dim3 grid(N2 / 64, BQ / 32);
        mma_gemm_kernel<1, 1><<<grid, 256, GEMM_SMEM>>>(
            x1, W2h, N1, N1, N1, b2, x2, nullptr, N2, 0);
    }

    // 4) head
    head_kernel<<<64, 256>>>(x2, W3, b3, mask, out);
}

// round 11
// speedup vs baseline: 1.1453x; 1.1453x over previous
#include <cuda_runtime.h>
#include <cuda_fp16.h>
#include <math.h>
#include <stdint.h>

// Problem constants
#define BB   32
#define LL   512
#define HH   1024
#define QQ   128
#define BQ   (BB * QQ)        // 4096 pair rows
#define K1   (3 * HH)          // 3072
#define N1   256               // VA_H
#define N2   128               // VA_H/2

// Scratch (static device globals)
__device__ __half g_A[(size_t)BQ * K1];     // pooled pair features, fp16
__device__ __half g_W1[(size_t)N1 * K1];    // fp16 weights
__device__ __half g_W2[(size_t)N2 * N1];
__device__ __half g_x1[(size_t)BQ * N1];    // gelu(layer1), fp16

// ---------------------------------------------------------------------------
// helpers
// ---------------------------------------------------------------------------
__device__ __forceinline__ uint32_t smem_u32(const void* p) {
    uint32_t a;
    asm("{ .reg .u64 t; cvta.to.shared.u64 t, %1; cvt.u32.u64 %0, t; }"
        : "=r"(a) : "l"(p));
    return a;
}

#define CP_ASYNC16(dst, src) \
    asm volatile("cp.async.cg.shared.global [%0], [%1], 16;" :: "r"(dst), "l"(src) : "memory")
#define CP_COMMIT() asm volatile("cp.async.commit_group;" ::: "memory")
#define CP_WAIT0()  asm volatile("cp.async.wait_group 0;" ::: "memory")
#define CP_WAIT1()  asm volatile("cp.async.wait_group 1;" ::: "memory")

__device__ __forceinline__ void mma16816(float c[4],
                                         const uint32_t a[4],
                                         const uint32_t b[2])
{
    asm volatile(
        "mma.sync.aligned.m16n8k16.row.col.f32.f16.f16.f32 "
        "{%0,%1,%2,%3}, {%4,%5,%6,%7}, {%8,%9}, {%0,%1,%2,%3};\n"
        : "+f"(c[0]), "+f"(c[1]), "+f"(c[2]), "+f"(c[3])
        : "r"(a[0]), "r"(a[1]), "r"(a[2]), "r"(a[3]),
          "r"(b[0]), "r"(b[1]));
}

__device__ __forceinline__ void ldsm4(uint32_t r[4], uint32_t addr)
{
    asm volatile("ldmatrix.sync.aligned.m8n8.x4.shared.b16 {%0,%1,%2,%3}, [%4];"
        : "=r"(r[0]), "=r"(r[1]), "=r"(r[2]), "=r"(r[3]) : "r"(addr));
}

__device__ __forceinline__ float gelu_exact(float x) {
    return 0.5f * x * (1.0f + erff(x * 0.70710678118654752f));
}

__device__ __forceinline__ void store_h4(__half* dst, size_t idx, float4 v)
{
    __half2 hh[2] = {
        __halves2half2(__float2half_rn(v.x), __float2half_rn(v.y)),
        __halves2half2(__float2half_rn(v.z), __float2half_rn(v.w)) };
    *(uint2*)(dst + idx) = *(uint2*)hh;
}

// ---------------------------------------------------------------------------
// Fused pooling + weight-prep kernel.
// blocks [0, BQ): span pooling + pair features -> fp16 g_A
// blocks [BQ, BQ+3072): convert W1 (and W2) fp32 -> fp16
// Span loop: fixed 8 iterations with predicated loads -> MLP=8.
// Span invariants: 0 <= e-s <= 7, s+7 <= 509 < LL (all addresses in bounds).
// ---------------------------------------------------------------------------
__global__ void pool_prep_kernel(const float* __restrict__ hs,
                                 const int* __restrict__ spans,
                                 const float* __restrict__ W1,
                                 const float* __restrict__ W2)
{
    if (blockIdx.x >= BQ) {
        const int i = (blockIdx.x - BQ) * 256 + threadIdx.x;
        if (i < N1 * K1) g_W1[i] = __float2half_rn(W1[i]);
        if (i < N2 * N1) g_W2[i] = __float2half_rn(W2[i]);
        return;
    }

    const int bq  = blockIdx.x;
    const int b   = bq >> 7;
    const int tid = threadIdx.x;

    const int* sp = spans + (size_t)bq * 4;
    const int as = sp[0], ae = sp[1], os = sp[2], oe = sp[3];
    const bool av = (as >= 2) && (ae >= as);
    const bool ov = (os >= 2) && (oe >= os);

    const float* base = hs + (size_t)b * LL * HH + 4 * tid;

    float4 aacc = {0.f, 0.f, 0.f, 0.f};
    float4 oacc = {0.f, 0.f, 0.f, 0.f};

    {
        const int s = av ? as : 1;
        const int e = av ? ae : 1;
        const float inv = 1.0f / (float)(e - s + 1);
        #pragma unroll
        for (int i = 0; i < 8; ++i) {
            const int r = s + i;
            if (r <= e) {
                const float4 v = *(const float4*)(base + (size_t)r * HH);
                aacc.x += v.x; aacc.y += v.y; aacc.z += v.z; aacc.w += v.w;
            }
        }
        aacc.x *= inv; aacc.y *= inv; aacc.z *= inv; aacc.w *= inv;
    }
    {
        const int s = ov ? os : 1;
        const int e = ov ? oe : 1;
        const float inv = 1.0f / (float)(e - s + 1);
        #pragma unroll
        for (int i = 0; i < 8; ++i) {
            const int r = s + i;
            if (r <= e) {
                const float4 v = *(const float4*)(base + (size_t)r * HH);
                oacc.x += v.x; oacc.y += v.y; oacc.z += v.z; oacc.w += v.w;
            }
        }
        oacc.x *= inv; oacc.y *= inv; oacc.z *= inv; oacc.w *= inv;
    }

    float4 pacc;
    pacc.x = aacc.x * oacc.x;  pacc.y = aacc.y * oacc.y;
    pacc.z = aacc.z * oacc.z;  pacc.w = aacc.w * oacc.w;

    const size_t rowoff = (size_t)bq * K1 + 4 * tid;
    store_h4(g_A, rowoff,          aacc);
    store_h4(g_A, rowoff + HH,     oacc);
    store_h4(g_A, rowoff + 2 * HH, pacc);
}

// ---------------------------------------------------------------------------
// Pipelined pure-fp16 mma.sync GEMM, fp32 accum, ldmatrix fragments.
// BM=32, BN=64*NTP, BK=32, 256 threads = 8 warps (2M x 4N).
// 2-stage cp.async double buffering.
// mode 1: out_h = gelu(acc+bias)  fp16
// mode 3: fused head — stage gelu(acc+bias) tile in smem, then per-row
//         dot with W3 (K=128), sigmoid*8+1, mask, write final output.
//         Requires BN == 128 (CTA owns complete rows).
// ---------------------------------------------------------------------------
template<int NTP, int MODE>
__global__ __launch_bounds__(256)
void mma_gemm_kernel(const __half* __restrict__ A,
                     const __half* __restrict__ B,
                     int lda, int ldb, int K,
                     const float* __restrict__ bias,
                     __half* __restrict__ out_h, int out_ld,
                     const float* __restrict__ W3,
                     const float* __restrict__ b3,
                     const float* __restrict__ mask,
                     float* __restrict__ out_final)
{
    constexpr int BM    = 32;
    constexpr int BN    = 64 * NTP;
    constexpr int AWd   = BM * 20;          // words per A buffer
    constexpr int BWd   = BN * 20;          // words per B buffer
    constexpr int STWd  = AWd + BWd;
    constexpr int TOT16 = (BM + BN) * 4;    // 16B units per stage
    constexpr int UNITS = (TOT16 + 255) / 256;

    extern __shared__ uint32_t sm[];
    const uint32_t smem32 = smem_u32(sm);

    const int tid   = threadIdx.x;
    const int warp  = tid >> 5;
    const int lane  = tid & 31;
    const int warpM = warp >> 2;
    const int warpN = warp & 3;
    const int lane4 = lane >> 2;
    const int lanem = lane & 3;

    const int m0 = blockIdx.y * BM;
    const int n0 = blockIdx.x * BN;
    const int nk = K >> 5;

    const uint32_t aLaneOff = ((lane & 15) * 20 + ((lane >> 4) << 2)) * 4;
    const uint32_t bLaneOff = (((lane & 7) + ((lane >> 4) << 3)) * 20
                               + (((lane >> 3) & 1) << 2)) * 4;
    const uint32_t aWarpOff = (uint32_t)(warpM * 16) * 80;
    const uint32_t bWarpOff = (uint32_t)(warpN * (NTP * 16)) * 80;

    auto load_stage = [&](int c) {
        const uint32_t sb = smem32 + (uint32_t)(c & 1) * (STWd * 4);
        const int kk = c * 32;
        #pragma unroll
        for (int i = 0; i < UNITS; ++i) {
            const int u = i * 256 + tid;
            if (UNITS * 256 != TOT16 && u >= TOT16) break;
            const __half* src;
            uint32_t dstw;
            if (u < BM * 4) {
                const int row = u >> 2, seg = u & 3;
                src  = A + (size_t)(m0 + row) * lda + kk + seg * 8;
                dstw = row * 20 + seg * 4;
            } else {
                const int v = u - BM * 4;
                const int row = v >> 2, seg = v & 3;
                src  = B + (size_t)(n0 + row) * ldb + kk + seg * 8;
                dstw = AWd + row * 20 + seg * 4;
            }
            CP_ASYNC16(sb + dstw * 4, src);
        }
        CP_COMMIT();
    };

    float acc[2 * NTP][4];
    #pragma unroll
    for (int j = 0; j < 2 * NTP; ++j)
        #pragma unroll
        for (int k = 0; k < 4; ++k) acc[j][k] = 0.f;

    load_stage(0);

    for (int c = 0; c < nk; ++c) {
        if (c + 1 < nk) { load_stage(c + 1); CP_WAIT1(); }
        else            { CP_WAIT0(); }
        __syncthreads();

        const uint32_t sb = smem32 + (uint32_t)(c & 1) * (STWd * 4);
        const uint32_t aB = sb + aWarpOff + aLaneOff;
        const uint32_t bB = sb + AWd * 4 + bWarpOff + bLaneOff;

        #pragma unroll
        for (int sub = 0; sub < 2; ++sub) {
            uint32_t af[4];
            ldsm4(af, aB + sub * 32);

            #pragma unroll
            for (int ntp = 0; ntp < NTP; ++ntp) {
                uint32_t bf[4];
                ldsm4(bf, bB + (uint32_t)ntp * (16 * 80) + sub * 32);
                #pragma unroll
                for (int hf = 0; hf < 2; ++hf)
                    mma16816(acc[ntp * 2 + hf], af, bf + hf * 2);
            }
        }
        __syncthreads();
    }

    // ---- epilogue: bias + gelu ----
    if (MODE == 1) {
        #pragma unroll
        for (int nt = 0; nt < 2 * NTP; ++nt) {
            const int c0 = n0 + warpN * (NTP * 16) + nt * 8 + lanem * 2;
            const int r0 = m0 + warpM * 16 + lane4;
            const float bv0 = bias[c0];
            const float bv1 = bias[c0 + 1];
            *(__half2*)(out_h + (size_t)r0 * out_ld + c0) =
                __halves2half2(__float2half_rn(gelu_exact(acc[nt][0] + bv0)),
                               __float2half_rn(gelu_exact(acc[nt][1] + bv1)));
            *(__half2*)(out_h + (size_t)(r0 + 8) * out_ld + c0) =
                __halves2half2(__float2half_rn(gelu_exact(acc[nt][2] + bv0)),
                               __float2half_rn(gelu_exact(acc[nt][3] + bv1)));
        }
    } else {
        // MODE 3: stage gelu'd x2 tile (32 x 128 fp32, pad 132) into smem
        float* xs = (float*)sm;
        __syncthreads();   // mainloop smem reads done before overwrite
        #pragma unroll
        for (int nt = 0; nt < 2 * NTP; ++nt) {
            const int cl = warpN * (NTP * 16) + nt * 8 + lanem * 2;  // 0..127
            const int rl = warpM * 16 + lane4;                        // 0..15
            const float bv0 = bias[n0 + cl];
            const float bv1 = bias[n0 + cl + 1];
            xs[rl * 132 + cl]           = gelu_exact(acc[nt][0] + bv0);
            xs[rl * 132 + cl + 1]       = gelu_exact(acc[nt][1] + bv1);
            xs[(rl + 8) * 132 + cl]     = gelu_exact(acc[nt][2] + bv0);
            xs[(rl + 8) * 132 + cl + 1] = gelu_exact(acc[nt][3] + bv1);
        }
        __syncthreads();

        // head: warp w handles local rows 4w..4w+3
        const float4 w0 = ((const float4*)W3)[lane];        // row 0 of W3
        const float4 w1 = ((const float4*)W3)[32 + lane];   // row 1 of W3
        const float b30 = b3[0], b31 = b3[1];

        #pragma unroll
        for (int i = 0; i < 4; ++i) {
            const int lr  = warp * 4 + i;
            const int row = m0 + lr;
            const float4 xv = *(const float4*)(xs + lr * 132 + lane * 4);
            float s0 = xv.x * w0.x + xv.y * w0.y + xv.z * w0.z + xv.w * w0.w;
            float s1 = xv.x * w1.x + xv.y * w1.y + xv.z * w1.z + xv.w * w1.w;
            #pragma unroll
            for (int off = 16; off > 0; off >>= 1) {
                s0 += __shfl_xor_sync(0xFFFFFFFFu, s0, off);
                s1 += __shfl_xor_sync(0xFFFFFFFFu, s1, off);
            }
            if (lane == 0) {
                const float mk = (mask[row] >= 0.5f) ? 1.0f : 0.0f;
                const float v0 = (1.0f / (1.0f + expf(-(s0 + b30)))) * 8.0f + 1.0f;
                const float v1 = (1.0f / (1.0f + expf(-(s1 + b31)))) * 8.0f + 1.0f;
                out_final[row * 2 + 0] = v0 * mk;
                out_final[row * 2 + 1] = v1 * mk;
            }
        }
    }
}

#define GEMM_SMEM ((2 * (32 * 20 + 128 * 20)) * 4)   // 25600 B (>= 32*132*4 head stage)

// ---------------------------------------------------------------------------
// Launch
// ---------------------------------------------------------------------------
extern "C" void kernel_launch(void* const* d_in, const int* in_sizes, int n_in,
                              void* d_out, int out_size)
{
    const float* hidden = (const float*)d_in[0];
    const int*   spans  = (const int*)d_in[1];
    const float* mask   = (const float*)d_in[2];
    const float* W1     = (const float*)d_in[3];
    const float* b1     = (const float*)d_in[4];
    const float* W2     = (const float*)d_in[5];
    const float* b2     = (const float*)d_in[6];
    const float* W3     = (const float*)d_in[7];
    const float* b3     = (const float*)d_in[8];
    float*       out    = (float*)d_out;

    __half *A, *W1h, *W2h, *x1;
    cudaGetSymbolAddress((void**)&A,   g_A);
    cudaGetSymbolAddress((void**)&W1h, g_W1);
    cudaGetSymbolAddress((void**)&W2h, g_W2);
    cudaGetSymbolAddress((void**)&x1,  g_x1);

    cudaFuncSetAttribute((const void*)mma_gemm_kernel<2, 1>,
                         cudaFuncAttributeMaxDynamicSharedMemorySize, GEMM_SMEM);
    cudaFuncSetAttribute((const void*)mma_gemm_kernel<2, 3>,
                         cudaFuncAttributeMaxDynamicSharedMemorySize, GEMM_SMEM);

    // 1) fused pooling (blocks 0..4095) + weight prep (blocks 4096..7167)
    pool_prep_kernel<<<BQ + (N1 * K1 + 255) / 256, 256>>>(hidden, spans, W1, W2);

    // 2) layer 1: grid (2, 128) = 256 CTAs, fused bias+gelu -> fp16 x1
    {
        dim3 grid(N1 / 128, BQ / 32);
        mma_gemm_kernel<2, 1><<<grid, 256, GEMM_SMEM>>>(
            A, W1h, K1, K1, K1, b1, x1, N1,
            nullptr, nullptr, nullptr, nullptr);
    }

    // 3) layer 2 + head fused: grid (1, 128) = 128 CTAs
    {
        dim3 grid(N2 / 128, BQ / 32);
        mma_gemm_kernel<2, 3><<<grid, 256, GEMM_SMEM>>>(
            x1, W2h, N1, N1, N1, b2, nullptr, 0,
            W3, b3, mask, out);
    }
}

// round 12
// speedup vs baseline: 1.1522x; 1.0060x over previous
#include <cuda_runtime.h>
#include <cuda_fp16.h>
#include <math.h>
#include <stdint.h>

// Problem constants
#define BB   32
#define LL   512
#define HH   1024
#define QQ   128
#define BQ   (BB * QQ)        // 4096 pair rows
#define K1   (3 * HH)          // 3072
#define N1   256               // VA_H
#define N2   128               // VA_H/2

// Scratch (static device globals)
__device__ __half g_A[(size_t)BQ * K1];     // pooled pair features, fp16
__device__ __half g_W1[(size_t)N1 * K1];    // fp16 weights
__device__ __half g_W2[(size_t)N2 * N1];
__device__ __half g_x1[(size_t)BQ * N1];    // gelu(layer1), fp16

// ---------------------------------------------------------------------------
// helpers
// ---------------------------------------------------------------------------
__device__ __forceinline__ uint32_t smem_u32(const void* p) {
    uint32_t a;
    asm("{ .reg .u64 t; cvta.to.shared.u64 t, %1; cvt.u32.u64 %0, t; }"
        : "=r"(a) : "l"(p));
    return a;
}

#define CP_ASYNC16(dst, src) \
    asm volatile("cp.async.cg.shared.global [%0], [%1], 16;" :: "r"(dst), "l"(src) : "memory")
#define CP_COMMIT() asm volatile("cp.async.commit_group;" ::: "memory")
#define CP_WAIT0()  asm volatile("cp.async.wait_group 0;" ::: "memory")
#define CP_WAIT1()  asm volatile("cp.async.wait_group 1;" ::: "memory")

__device__ __forceinline__ void mma16816(float c[4],
                                         const uint32_t a[4],
                                         const uint32_t b[2])
{
    asm volatile(
        "mma.sync.aligned.m16n8k16.row.col.f32.f16.f16.f32 "
        "{%0,%1,%2,%3}, {%4,%5,%6,%7}, {%8,%9}, {%0,%1,%2,%3};\n"
        : "+f"(c[0]), "+f"(c[1]), "+f"(c[2]), "+f"(c[3])
        : "r"(a[0]), "r"(a[1]), "r"(a[2]), "r"(a[3]),
          "r"(b[0]), "r"(b[1]));
}

__device__ __forceinline__ void ldsm4(uint32_t r[4], uint32_t addr)
{
    asm volatile("ldmatrix.sync.aligned.m8n8.x4.shared.b16 {%0,%1,%2,%3}, [%4];"
        : "=r"(r[0]), "=r"(r[1]), "=r"(r[2]), "=r"(r[3]) : "r"(addr));
}

__device__ __forceinline__ float gelu_exact(float x) {
    return 0.5f * x * (1.0f + erff(x * 0.70710678118654752f));
}

__device__ __forceinline__ void store_h4(__half* dst, size_t idx, float4 v)
{
    __half2 hh[2] = {
        __halves2half2(__float2half_rn(v.x), __float2half_rn(v.y)),
        __halves2half2(__float2half_rn(v.z), __float2half_rn(v.w)) };
    *(uint2*)(dst + idx) = *(uint2*)hh;
}

// ---------------------------------------------------------------------------
// Fused pooling + weight-prep kernel (as R11).
// ---------------------------------------------------------------------------
__global__ void pool_prep_kernel(const float* __restrict__ hs,
                                 const int* __restrict__ spans,
                                 const float* __restrict__ W1,
                                 const float* __restrict__ W2)
{
    if (blockIdx.x >= BQ) {
        const int i = (blockIdx.x - BQ) * 256 + threadIdx.x;
        if (i < N1 * K1) g_W1[i] = __float2half_rn(W1[i]);
        if (i < N2 * N1) g_W2[i] = __float2half_rn(W2[i]);
        return;
    }

    const int bq  = blockIdx.x;
    const int b   = bq >> 7;
    const int tid = threadIdx.x;

    const int* sp = spans + (size_t)bq * 4;
    const int as = sp[0], ae = sp[1], os = sp[2], oe = sp[3];
    const bool av = (as >= 2) && (ae >= as);
    const bool ov = (os >= 2) && (oe >= os);

    const float* base = hs + (size_t)b * LL * HH + 4 * tid;

    float4 aacc = {0.f, 0.f, 0.f, 0.f};
    float4 oacc = {0.f, 0.f, 0.f, 0.f};

    {
        const int s = av ? as : 1;
        const int e = av ? ae : 1;
        const float inv = 1.0f / (float)(e - s + 1);
        #pragma unroll
        for (int i = 0; i < 8; ++i) {
            const int r = s + i;
            if (r <= e) {
                const float4 v = *(const float4*)(base + (size_t)r * HH);
                aacc.x += v.x; aacc.y += v.y; aacc.z += v.z; aacc.w += v.w;
            }
        }
        aacc.x *= inv; aacc.y *= inv; aacc.z *= inv; aacc.w *= inv;
    }
    {
        const int s = ov ? os : 1;
        const int e = ov ? oe : 1;
        const float inv = 1.0f / (float)(e - s + 1);
        #pragma unroll
        for (int i = 0; i < 8; ++i) {
            const int r = s + i;
            if (r <= e) {
                const float4 v = *(const float4*)(base + (size_t)r * HH);
                oacc.x += v.x; oacc.y += v.y; oacc.z += v.z; oacc.w += v.w;
            }
        }
        oacc.x *= inv; oacc.y *= inv; oacc.z *= inv; oacc.w *= inv;
    }

    float4 pacc;
    pacc.x = aacc.x * oacc.x;  pacc.y = aacc.y * oacc.y;
    pacc.z = aacc.z * oacc.z;  pacc.w = aacc.w * oacc.w;

    const size_t rowoff = (size_t)bq * K1 + 4 * tid;
    store_h4(g_A, rowoff,          aacc);
    store_h4(g_A, rowoff + HH,     oacc);
    store_h4(g_A, rowoff + 2 * HH, pacc);
}

// ---------------------------------------------------------------------------
// Pipelined pure-fp16 mma.sync GEMM, fp32 accum, ldmatrix fragments.
// BM=32, BN=64*NTP, 256 threads = 8 warps (2M x 4N).
// Each pipeline stage covers TWO 32-wide K-chunks (64 K per barrier window);
// per-chunk smem layout is the proven conflict-free 20-word-row scheme.
// 2-stage cp.async double buffering.
// mode 1: out_h = gelu(acc+bias)  fp16
// mode 3: fused head (requires BN == 128)
// ---------------------------------------------------------------------------
template<int NTP, int MODE>
__global__ __launch_bounds__(256)
void mma_gemm_kernel(const __half* __restrict__ A,
                     const __half* __restrict__ B,
                     int lda, int ldb, int K,
                     const float* __restrict__ bias,
                     __half* __restrict__ out_h, int out_ld,
                     const float* __restrict__ W3,
                     const float* __restrict__ b3,
                     const float* __restrict__ mask,
                     float* __restrict__ out_final)
{
    constexpr int BM    = 32;
    constexpr int BN    = 64 * NTP;
    constexpr int AWd   = BM * 20;          // words per A chunk buffer
    constexpr int BWd   = BN * 20;          // words per B chunk buffer
    constexpr int CHWd  = AWd + BWd;        // words per chunk
    constexpr int STWd  = 2 * CHWd;         // words per stage (2 chunks)
    constexpr int TOT16 = (BM + BN) * 4;    // 16B units per chunk
    constexpr int UNITS = (TOT16 + 255) / 256;

    extern __shared__ uint32_t sm[];
    const uint32_t smem32 = smem_u32(sm);

    const int tid   = threadIdx.x;
    const int warp  = tid >> 5;
    const int lane  = tid & 31;
    const int warpM = warp >> 2;
    const int warpN = warp & 3;
    const int lane4 = lane >> 2;
    const int lanem = lane & 3;

    const int m0 = blockIdx.y * BM;
    const int n0 = blockIdx.x * BN;
    const int ns = K >> 6;                  // stages of 64 K

    const uint32_t aLaneOff = ((lane & 15) * 20 + ((lane >> 4) << 2)) * 4;
    const uint32_t bLaneOff = (((lane & 7) + ((lane >> 4) << 3)) * 20
                               + (((lane >> 3) & 1) << 2)) * 4;
    const uint32_t aWarpOff = (uint32_t)(warpM * 16) * 80;
    const uint32_t bWarpOff = (uint32_t)(warpN * (NTP * 16)) * 80;

    auto load_stage = [&](int s) {
        const uint32_t sb = smem32 + (uint32_t)(s & 1) * (STWd * 4);
        #pragma unroll
        for (int ch = 0; ch < 2; ++ch) {
            const int kk = (2 * s + ch) * 32;
            const uint32_t cb = sb + (uint32_t)ch * (CHWd * 4);
            #pragma unroll
            for (int i = 0; i < UNITS; ++i) {
                const int u = i * 256 + tid;
                if (UNITS * 256 != TOT16 && u >= TOT16) break;
                const __half* src;
                uint32_t dstw;
                if (u < BM * 4) {
                    const int row = u >> 2, seg = u & 3;
                    src  = A + (size_t)(m0 + row) * lda + kk + seg * 8;
                    dstw = row * 20 + seg * 4;
                } else {
                    const int v = u - BM * 4;
                    const int row = v >> 2, seg = v & 3;
                    src  = B + (size_t)(n0 + row) * ldb + kk + seg * 8;
                    dstw = AWd + row * 20 + seg * 4;
                }
                CP_ASYNC16(cb + dstw * 4, src);
            }
        }
        CP_COMMIT();
    };

    float acc[2 * NTP][4];
    #pragma unroll
    for (int j = 0; j < 2 * NTP; ++j)
        #pragma unroll
        for (int k = 0; k < 4; ++k) acc[j][k] = 0.f;

    load_stage(0);

    for (int s = 0; s < ns; ++s) {
        if (s + 1 < ns) { load_stage(s + 1); CP_WAIT1(); }
        else            { CP_WAIT0(); }
        __syncthreads();

        const uint32_t sb = smem32 + (uint32_t)(s & 1) * (STWd * 4);

        #pragma unroll
        for (int ch = 0; ch < 2; ++ch) {
            const uint32_t cb = sb + (uint32_t)ch * (CHWd * 4);
            const uint32_t aB = cb + aWarpOff + aLaneOff;
            const uint32_t bB = cb + AWd * 4 + bWarpOff + bLaneOff;

            #pragma unroll
            for (int sub = 0; sub < 2; ++sub) {
                uint32_t af[4];
                ldsm4(af, aB + sub * 32);

                #pragma unroll
                for (int ntp = 0; ntp < NTP; ++ntp) {
                    uint32_t bf[4];
                    ldsm4(bf, bB + (uint32_t)ntp * (16 * 80) + sub * 32);
                    #pragma unroll
                    for (int hf = 0; hf < 2; ++hf)
                        mma16816(acc[ntp * 2 + hf], af, bf + hf * 2);
                }
            }
        }
        __syncthreads();
    }

    // ---- epilogue ----
    if (MODE == 1) {
        #pragma unroll
        for (int nt = 0; nt < 2 * NTP; ++nt) {
            const int c0 = n0 + warpN * (NTP * 16) + nt * 8 + lanem * 2;
            const int r0 = m0 + warpM * 16 + lane4;
            const float bv0 = bias[c0];
            const float bv1 = bias[c0 + 1];
            *(__half2*)(out_h + (size_t)r0 * out_ld + c0) =
                __halves2half2(__float2half_rn(gelu_exact(acc[nt][0] + bv0)),
                               __float2half_rn(gelu_exact(acc[nt][1] + bv1)));
            *(__half2*)(out_h + (size_t)(r0 + 8) * out_ld + c0) =
                __halves2half2(__float2half_rn(gelu_exact(acc[nt][2] + bv0)),
                               __float2half_rn(gelu_exact(acc[nt][3] + bv1)));
        }
    } else {
        // MODE 3: stage gelu'd x2 tile (32 x 128 fp32, pad 132) into smem
        float* xs = (float*)sm;
        __syncthreads();   // mainloop smem reads done before overwrite
        #pragma unroll
        for (int nt = 0; nt < 2 * NTP; ++nt) {
            const int cl = warpN * (NTP * 16) + nt * 8 + lanem * 2;  // 0..127
            const int rl = warpM * 16 + lane4;                        // 0..15
            const float bv0 = bias[n0 + cl];
            const float bv1 = bias[n0 + cl + 1];
            xs[rl * 132 + cl]           = gelu_exact(acc[nt][0] + bv0);
            xs[rl * 132 + cl + 1]       = gelu_exact(acc[nt][1] + bv1);
            xs[(rl + 8) * 132 + cl]     = gelu_exact(acc[nt][2] + bv0);
            xs[(rl + 8) * 132 + cl + 1] = gelu_exact(acc[nt][3] + bv1);
        }
        __syncthreads();

        // head: warp w handles local rows 4w..4w+3
        const float4 w0 = ((const float4*)W3)[lane];        // row 0 of W3
        const float4 w1 = ((const float4*)W3)[32 + lane];   // row 1 of W3
        const float b30 = b3[0], b31 = b3[1];

        #pragma unroll
        for (int i = 0; i < 4; ++i) {
            const int lr  = warp * 4 + i;
            const int row = m0 + lr;
            const float4 xv = *(const float4*)(xs + lr * 132 + lane * 4);
            float s0 = xv.x * w0.x + xv.y * w0.y + xv.z * w0.z + xv.w * w0.w;
            float s1 = xv.x * w1.x + xv.y * w1.y + xv.z * w1.z + xv.w * w1.w;
            #pragma unroll
            for (int off = 16; off > 0; off >>= 1) {
                s0 += __shfl_xor_sync(0xFFFFFFFFu, s0, off);
                s1 += __shfl_xor_sync(0xFFFFFFFFu, s1, off);
            }
            if (lane == 0) {
                const float mk = (mask[row] >= 0.5f) ? 1.0f : 0.0f;
                const float v0 = (1.0f / (1.0f + expf(-(s0 + b30)))) * 8.0f + 1.0f;
                const float v1 = (1.0f / (1.0f + expf(-(s1 + b31)))) * 8.0f + 1.0f;
                out_final[row * 2 + 0] = v0 * mk;
                out_final[row * 2 + 1] = v1 * mk;
            }
        }
    }
}

// 2 stages x 2 chunks x (32+128)*20 words * 4 B = 51200 B
#define GEMM_SMEM (2 * 2 * (32 * 20 + 128 * 20) * 4)

// ---------------------------------------------------------------------------
// Launch
// ---------------------------------------------------------------------------
extern "C" void kernel_launch(void* const* d_in, const int* in_sizes, int n_in,
                              void* d_out, int out_size)
{
    const float* hidden = (const float*)d_in[0];
    const int*   spans  = (const int*)d_in[1];
    const float* mask   = (const float*)d_in[2];
    const float* W1     = (const float*)d_in[3];
    const float* b1     = (const float*)d_in[4];
    const float* W2     = (const float*)d_in[5];
    const float* b2     = (const float*)d_in[6];
    const float* W3     = (const float*)d_in[7];
    const float* b3     = (const float*)d_in[8];
    float*       out    = (float*)d_out;

    __half *A, *W1h, *W2h, *x1;
    cudaGetSymbolAddress((void**)&A,   g_A);
    cudaGetSymbolAddress((void**)&W1h, g_W1);
    cudaGetSymbolAddress((void**)&W2h, g_W2);
    cudaGetSymbolAddress((void**)&x1,  g_x1);

    cudaFuncSetAttribute((const void*)mma_gemm_kernel<2, 1>,
                         cudaFuncAttributeMaxDynamicSharedMemorySize, GEMM_SMEM);
    cudaFuncSetAttribute((const void*)mma_gemm_kernel<2, 3>,
                         cudaFuncAttributeMaxDynamicSharedMemorySize, GEMM_SMEM);

    // 1) fused pooling (blocks 0..4095) + weight prep (blocks 4096..7167)
    pool_prep_kernel<<<BQ + (N1 * K1 + 255) / 256, 256>>>(hidden, spans, W1, W2);

    // 2) layer 1: grid (2, 128) = 256 CTAs, fused bias+gelu -> fp16 x1
    {
        dim3 grid(N1 / 128, BQ / 32);
        mma_gemm_kernel<2, 1><<<grid, 256, GEMM_SMEM>>>(
            A, W1h, K1, K1, K1, b1, x1, N1,
            nullptr, nullptr, nullptr, nullptr);
    }

    // 3) layer 2 + head fused: grid (1, 128) = 128 CTAs
    {
        dim3 grid(N2 / 128, BQ / 32);
        mma_gemm_kernel<2, 3><<<grid, 256, GEMM_SMEM>>>(
            x1, W2h, N1, N1, N1, b2, nullptr, 0,
            W3, b3, mask, out);
    }
}